// round 15
// baseline (speedup 1.0000x reference)
#include <cuda_runtime.h>
#include <cstddef>

// GazeLSTM on GB300 (sm_103a). B=16384, T=128, half=64.
// Single kernel, 64-thread blocks:
//  * blocks [0, nfused): 32 b's. warp0 = backward-chain producer (stages R,
//    matvec-T, writes double-buffered sout + gmem rows 0..half-1); warp1 =
//    LSTM consumer (register weights, reads sout one chunk behind, writes
//    row half). One __syncthreads per chunk; producer always a chunk ahead.
//  * blocks [nfused, ..): 2 independent forward-chain warps x 32 b's.

#define BT  32      // b's per warp
#define C   8       // matrices per chunk
#define NQ  18      // float4 per b per chain chunk

__device__ __forceinline__ unsigned long long pk2(float lo, float hi) {
    unsigned long long r; asm("mov.b64 %0, {%1, %2};" : "=l"(r) : "f"(lo), "f"(hi)); return r;
}
__device__ __forceinline__ void upk2(float& lo, float& hi, unsigned long long v) {
    asm("mov.b64 {%0, %1}, %2;" : "=f"(lo), "=f"(hi) : "l"(v));
}
__device__ __forceinline__ unsigned long long fma2(unsigned long long a, unsigned long long b, unsigned long long c) {
    unsigned long long d; asm("fma.rn.f32x2 %0, %1, %2, %3;" : "=l"(d) : "l"(a), "l"(b), "l"(c)); return d;
}
__device__ __forceinline__ float tanhx(float x) {
    float y; asm("tanh.approx.f32 %0, %1;" : "=f"(y) : "f"(x)); return y;
}

#define CP16(dst_u32, src_ptr) \
    asm volatile("cp.async.cg.shared.global [%0], [%1], 16;" :: "r"(dst_u32), "l"(src_ptr))
#define CP_COMMIT() asm volatile("cp.async.commit_group;")
#define CP_WAIT1()  asm volatile("cp.async.wait_group 1;")
#define CP_WAIT0()  asm volatile("cp.async.wait_group 0;")

// Stage chain chunk: 32 b's x NQ quads, 18 CP16/lane. j0 % 4 == 0 required.
__device__ __forceinline__ void stage_chain(float4* __restrict__ sdst,
                                            const float4* __restrict__ src4base,
                                            int t9q, int lane) {
    int bp = lane / NQ;
    int q  = lane - bp * NQ;
#pragma unroll
    for (int k = 0; k < NQ; k++) {
        const float4* src = src4base + (size_t)bp * t9q + q;
        unsigned dst = (unsigned)__cvta_generic_to_shared(sdst + q * BT + (bp ^ q));
        CP16(dst, src);
        q += 14; bp += 1;                 // advance 32 = 1*18 + 14
        if (q >= NQ) { q -= NQ; bp += 1; }
    }
}

template <int M>
__device__ __forceinline__ void loadA(float* A, const float4* __restrict__ buf, int lane) {
    constexpr int F0 = 9 * M, QA = F0 >> 2, OFF = F0 & 3;
    float tmp[12];
    *(float4*)(tmp + 0) = buf[(QA + 0) * BT + (lane ^ (QA + 0))];
    *(float4*)(tmp + 4) = buf[(QA + 1) * BT + (lane ^ (QA + 1))];
    *(float4*)(tmp + 8) = buf[(QA + 2) * BT + (lane ^ (QA + 2))];
#pragma unroll
    for (int i = 0; i < 9; i++) A[i] = tmp[OFF + i];
}

// Coalesced writeback: NF floats/b for 32 b's from swizzled sout.
template <int NF>
__device__ __forceinline__ void store_chain(float* __restrict__ gdst, size_t T3,
                                            const float* __restrict__ sout, int lane) {
    int bp = lane / NF;
    int e  = lane - bp * NF;
    constexpr int DB = BT / NF;
    constexpr int DE = BT % NF;
#pragma unroll
    for (int k = 0; k < NF; k++) {
        gdst[(size_t)bp * T3 + e] = sout[e * BT + (bp ^ e)];
        bp += DB; e += DE;
        if (e >= NF) { e -= NF; bp += 1; }
    }
}

// LSTM step, register weights (prescaled: sigmoid gates x0.5;
// sig(x)=0.5+0.5*tanh(x/2)). R13's measured-best form.
#define LSTM_STEP(x0, x1, x2)                                                        \
    do {                                                                             \
        unsigned long long xx0 = pk2((x0), (x0)), xx1 = pk2((x1), (x1)), xx2 = pk2((x2), (x2)); \
        unsigned long long hh0 = pk2(h0, h0), hh1 = pk2(h1, h1), hh2 = pk2(h2, h2);  \
        float th[12];                                                                \
        _Pragma("unroll") for (int p = 0; p < 6; p++) {                              \
            unsigned long long xp = fma2(WI[p][0], xx0, fma2(WI[p][1], xx1, fma2(WI[p][2], xx2, BS[p]))); \
            unsigned long long g  = fma2(WH[p][0], hh0, fma2(WH[p][1], hh1, fma2(WH[p][2], hh2, xp)));    \
            float a_, b_; upk2(a_, b_, g);                                           \
            th[2*p] = tanhx(a_); th[2*p+1] = tanhx(b_);                              \
        }                                                                            \
        float i0 = fmaf(0.5f, th[0], 0.5f), i1 = fmaf(0.5f, th[1], 0.5f), i2 = fmaf(0.5f, th[2], 0.5f); \
        float f0 = fmaf(0.5f, th[3], 0.5f), f1 = fmaf(0.5f, th[4], 0.5f), f2 = fmaf(0.5f, th[5], 0.5f); \
        float o0 = fmaf(0.5f, th[9], 0.5f), o1 = fmaf(0.5f, th[10], 0.5f), o2 = fmaf(0.5f, th[11], 0.5f); \
        c0 = fmaf(f0, c0, i0 * th[6]);                                               \
        c1 = fmaf(f1, c1, i1 * th[7]);                                               \
        c2 = fmaf(f2, c2, i2 * th[8]);                                               \
        h0 = o0 * tanhx(c0); h1 = o1 * tanhx(c1); h2 = o2 * tanhx(c2);               \
    } while (0)

__global__ __launch_bounds__(64) void gaze_kernel(
    const float* __restrict__ dir, const float* __restrict__ R,
    const float* __restrict__ Wih, const float* __restrict__ Whh,
    const float* __restrict__ bih, const float* __restrict__ bhh,
    float* __restrict__ out, int B, int T, int nfused)
{
    __shared__ float4 sbufA[2][NQ * BT];          // 18432 B
    __shared__ float4 sbufB[2][NQ * BT];          // 18432 B (fwd warp1 only)
    __shared__ float  sout2[2][3 * C * BT];       // 6144 B  (double buffer)

    const int half = T >> 1;
    const int t9q = (T * 9) >> 2;
    const size_t T3 = (size_t)T * 3;
    const int tid = threadIdx.x;
    const int lane = tid & 31;
    const int w = tid >> 5;
    const int nchunks = half / C;                 // 8

    if ((int)blockIdx.x < nfused) {
        // ============ fused block: 32 b's, producer + consumer warps ============
        const int bbase = blockIdx.x * BT;

        if (w == 0) {
            // ---- producer: backward chain ----
            float v0 = __ldg(dir + (size_t)(bbase + lane) * 3 + 0);
            float v1 = __ldg(dir + (size_t)(bbase + lane) * 3 + 1);
            float v2 = __ldg(dir + (size_t)(bbase + lane) * 3 + 2);

            const float4* R4 = (const float4*)R + (size_t)bbase * t9q;
            float* oblk = out + (size_t)bbase * T3;

            stage_chain(sbufA[0], R4 + (((half - C) * 9) >> 2), t9q, lane);
            CP_COMMIT();
            for (int cc = 0; cc < nchunks; cc++) {
                if (cc + 1 < nchunks) {
                    stage_chain(sbufA[(cc + 1) & 1], R4 + (((half - C * (cc + 2)) * 9) >> 2), t9q, lane);
                    CP_COMMIT(); CP_WAIT1();
                } else CP_WAIT0();
                __syncwarp();

                const float4* buf = sbufA[cc & 1];
                float* so = sout2[cc & 1];
#pragma unroll
                for (int s = 0; s < C; s++) {
                    float A[9];
                    switch (s) {   // matrix slot 7-s (reverse within chunk)
                        case 0: loadA<7>(A, buf, lane); break;
                        case 1: loadA<6>(A, buf, lane); break;
                        case 2: loadA<5>(A, buf, lane); break;
                        case 3: loadA<4>(A, buf, lane); break;
                        case 4: loadA<3>(A, buf, lane); break;
                        case 5: loadA<2>(A, buf, lane); break;
                        case 6: loadA<1>(A, buf, lane); break;
                        default: loadA<0>(A, buf, lane); break;
                    }
                    // v = A^T v
                    float n0 = fmaf(A[6], v2, fmaf(A[3], v1, A[0] * v0));
                    float n1 = fmaf(A[7], v2, fmaf(A[4], v1, A[1] * v0));
                    float n2 = fmaf(A[8], v2, fmaf(A[5], v1, A[2] * v0));
                    v0 = n0; v1 = n1; v2 = n2;
                    const int eo = 3 * s;
                    so[(eo + 0) * BT + (lane ^ (eo + 0))] = v0;
                    so[(eo + 1) * BT + (lane ^ (eo + 1))] = v1;
                    so[(eo + 2) * BT + (lane ^ (eo + 2))] = v2;
                }
                __syncwarp();
                store_chain<3 * C>(oblk + (size_t)(C * cc) * 3, T3, so, lane);
                __syncthreads();               // publish chunk cc to consumer
            }
        } else {
            // ---- consumer: LSTM over back-chain outputs ----
            unsigned long long WI[6][3], WH[6][3], BS[6];
#pragma unroll
            for (int p = 0; p < 6; p++) {
                const int g0 = 2 * p, g1 = 2 * p + 1;
                const float s0 = (g0 >= 6 && g0 <= 8) ? 1.0f : 0.5f;
                const float s1 = (g1 >= 6 && g1 <= 8) ? 1.0f : 0.5f;
#pragma unroll
                for (int j = 0; j < 3; j++) {
                    WI[p][j] = pk2(__ldg(Wih + g0*3 + j) * s0, __ldg(Wih + g1*3 + j) * s1);
                    WH[p][j] = pk2(__ldg(Whh + g0*3 + j) * s0, __ldg(Whh + g1*3 + j) * s1);
                }
                BS[p] = pk2((__ldg(bih + g0) + __ldg(bhh + g0)) * s0,
                            (__ldg(bih + g1) + __ldg(bhh + g1)) * s1);
            }

            const float d0 = __ldg(dir + (size_t)(bbase + lane) * 3 + 0);
            const float d1 = __ldg(dir + (size_t)(bbase + lane) * 3 + 1);
            const float d2 = __ldg(dir + (size_t)(bbase + lane) * 3 + 2);
            float h0 = 0.f, h1 = 0.f, h2 = 0.f, c0 = 0.f, c1 = 0.f, c2 = 0.f;

            for (int cc = 0; cc < nchunks; cc++) {
                __syncthreads();               // wait for producer chunk cc
                const float* so = sout2[cc & 1];
#pragma unroll
                for (int s = 0; s < C; s++) {
                    const int eo = 3 * s;
                    float x0 = so[(eo + 0) * BT + (lane ^ (eo + 0))];
                    float x1 = so[(eo + 1) * BT + (lane ^ (eo + 1))];
                    float x2 = so[(eo + 2) * BT + (lane ^ (eo + 2))];
                    LSTM_STEP(x0, x1, x2);
                }
            }
            // final step consumes dir; write row t = half
            LSTM_STEP(d0, d1, d2);
            float* ob = out + (size_t)(bbase + lane) * T3 + (size_t)half * 3;
            ob[0] = h0; ob[1] = h1; ob[2] = h2;
        }
    } else {
        // ============ forward block: 2 independent warps x 32 b's ============
        const int bbase = ((int)blockIdx.x - nfused) * 64 + w * BT;
        const int nsteps = T - 1 - half;           // 63

        float4* sb = (w == 0) ? &sbufA[0][0] : &sbufB[0][0];
        float4* bufs[2] = { sb, sb + NQ * BT };
        float* so = sout2[w];

        float v0 = __ldg(dir + (size_t)(bbase + lane) * 3 + 0);
        float v1 = __ldg(dir + (size_t)(bbase + lane) * 3 + 1);
        float v2 = __ldg(dir + (size_t)(bbase + lane) * 3 + 2);

        const float4* R4 = (const float4*)R + (size_t)bbase * t9q;
        float* oblk = out + (size_t)bbase * T3;

        stage_chain(bufs[0], R4 + ((half * 9) >> 2), t9q, lane);
        CP_COMMIT();
        for (int cc = 0; cc < nchunks; cc++) {
            if (cc + 1 < nchunks) {
                stage_chain(bufs[(cc + 1) & 1], R4 + (((half + C * (cc + 1)) * 9) >> 2), t9q, lane);
                CP_COMMIT(); CP_WAIT1();
            } else CP_WAIT0();
            __syncwarp();

            const float4* buf = bufs[cc & 1];
            const int ns = (nsteps - C * cc) < C ? (nsteps - C * cc) : C;
#pragma unroll
            for (int s = 0; s < C; s++) {
                if (s < ns) {
                    float A[9];
                    switch (s) {
                        case 0: loadA<0>(A, buf, lane); break;
                        case 1: loadA<1>(A, buf, lane); break;
                        case 2: loadA<2>(A, buf, lane); break;
                        case 3: loadA<3>(A, buf, lane); break;
                        case 4: loadA<4>(A, buf, lane); break;
                        case 5: loadA<5>(A, buf, lane); break;
                        case 6: loadA<6>(A, buf, lane); break;
                        default: loadA<7>(A, buf, lane); break;
                    }
                    // v = A v
                    float n0 = fmaf(A[2], v2, fmaf(A[1], v1, A[0] * v0));
                    float n1 = fmaf(A[5], v2, fmaf(A[4], v1, A[3] * v0));
                    float n2 = fmaf(A[8], v2, fmaf(A[7], v1, A[6] * v0));
                    v0 = n0; v1 = n1; v2 = n2;
                    const int eo = 3 * s;
                    so[(eo + 0) * BT + (lane ^ (eo + 0))] = v0;
                    so[(eo + 1) * BT + (lane ^ (eo + 1))] = v1;
                    so[(eo + 2) * BT + (lane ^ (eo + 2))] = v2;
                }
            }
            __syncwarp();
            float* gdst = oblk + (size_t)(half + 1 + C * cc) * 3;
            if (ns == C) store_chain<3 * C>(gdst, T3, so, lane);
            else         store_chain<21>(gdst, T3, so, lane);   // last: 7 steps
            __syncwarp();
        }
    }
}

extern "C" void kernel_launch(void* const* d_in, const int* in_sizes, int n_in,
                              void* d_out, int out_size)
{
    const float* dir = (const float*)d_in[0];
    const float* R   = (const float*)d_in[1];
    const float* Wih = (const float*)d_in[2];
    const float* Whh = (const float*)d_in[3];
    const float* bih = (const float*)d_in[4];
    const float* bhh = (const float*)d_in[5];
    float* out = (float*)d_out;

    const int B = in_sizes[0] / 3;
    const int T = in_sizes[1] / (B * 9);
    const int nfused = B / 32;    // 512
    const int nfwd   = B / 64;    // 256

    gaze_kernel<<<nfused + nfwd, 64>>>(dir, R, Wih, Whh, bih, bhh, out, B, T, nfused);
}

// round 16
// speedup vs baseline: 1.4115x; 1.4115x over previous
#include <cuda_runtime.h>
#include <cstddef>

// GazeLSTM on GB300 (sm_103a). B=16384, T=128, half=64.
// R13 structure with fully SCALAR LSTM (no f32x2 packing — A/B test of FFMA2
// packing overhead). Single kernel, 32-thread (1-warp) blocks:
//  * blocks [0, nback): backward chain + fused LSTM, 2x4 inner loop, scalar
//    register weights. Writes rows 0..half-1 and row half.
//  * blocks [nback, ..): forward chain (unchanged). Writes rows half+1..T-1.

#define BT  32      // b's per block (one warp)
#define C   8       // matrices per chunk
#define NQ  18      // float4 per b per chain chunk

__device__ __forceinline__ float tanhx(float x) {
    float y; asm("tanh.approx.f32 %0, %1;" : "=f"(y) : "f"(x)); return y;
}

#define CP16(dst_u32, src_ptr) \
    asm volatile("cp.async.cg.shared.global [%0], [%1], 16;" :: "r"(dst_u32), "l"(src_ptr))
#define CP_COMMIT() asm volatile("cp.async.commit_group;")
#define CP_WAIT1()  asm volatile("cp.async.wait_group 1;")
#define CP_WAIT0()  asm volatile("cp.async.wait_group 0;")

// Stage chain chunk: 32 b's x NQ quads, 18 CP16/thread. j0 % 4 == 0 required.
__device__ __forceinline__ void stage_chain(float4* __restrict__ sdst,
                                            const float4* __restrict__ src4base,
                                            int t9q, int tid) {
    int bp = tid / NQ;
    int q  = tid - bp * NQ;
#pragma unroll
    for (int k = 0; k < NQ; k++) {
        const float4* src = src4base + (size_t)bp * t9q + q;
        unsigned dst = (unsigned)__cvta_generic_to_shared(sdst + q * BT + (bp ^ q));
        CP16(dst, src);
        q += 14; bp += 1;                 // advance 32 = 1*18 + 14
        if (q >= NQ) { q -= NQ; bp += 1; }
    }
}

// Compile-time M (forward branch).
template <int M>
__device__ __forceinline__ void loadA(float* A, const float4* __restrict__ buf, int tid) {
    constexpr int F0 = 9 * M, QA = F0 >> 2, OFF = F0 & 3;
    float tmp[12];
    *(float4*)(tmp + 0) = buf[(QA + 0) * BT + (tid ^ (QA + 0))];
    *(float4*)(tmp + 4) = buf[(QA + 1) * BT + (tid ^ (QA + 1))];
    *(float4*)(tmp + 8) = buf[(QA + 2) * BT + (tid ^ (QA + 2))];
#pragma unroll
    for (int i = 0; i < 9; i++) A[i] = tmp[OFF + i];
}

// Runtime quad base (qa < 16), compile-time byte offset within first quad.
template <int OFF>
__device__ __forceinline__ void loadA_r(float* A, const float4* __restrict__ buf,
                                        int qa, int tid) {
    float tmp[12];
    *(float4*)(tmp + 0) = buf[(qa + 0) * BT + (tid ^ (qa + 0))];
    *(float4*)(tmp + 4) = buf[(qa + 1) * BT + (tid ^ (qa + 1))];
    *(float4*)(tmp + 8) = buf[(qa + 2) * BT + (tid ^ (qa + 2))];
#pragma unroll
    for (int i = 0; i < 9; i++) A[i] = tmp[OFF + i];
}

// Coalesced writeback: NF floats/b for 32 b's from swizzled sout.
template <int NF>
__device__ __forceinline__ void store_chain(float* __restrict__ gdst, size_t T3,
                                            const float* __restrict__ sout, int tid) {
    int bp = tid / NF;
    int e  = tid - bp * NF;
    constexpr int DB = BT / NF;
    constexpr int DE = BT % NF;
#pragma unroll
    for (int k = 0; k < NF; k++) {
        gdst[(size_t)bp * T3 + e] = sout[e * BT + (bp ^ e)];
        bp += DB; e += DE;
        if (e >= NF) { e -= NF; bp += 1; }
    }
}

// SCALAR LSTM step. Weights prescaled: sigmoid-gate rows (g<6 or g>=9) x0.5,
// tanh-gate rows (6..8) x1. sig(x) = 0.5 + 0.5*tanh(x/2).
// WIs[g][3], WHs[g][3], BSs[g] for g in 0..11 (i0..2, f0..2, g0..2, o0..2).
#define LSTM_STEP(x0, x1, x2)                                                        \
    do {                                                                             \
        float th[12];                                                                \
        _Pragma("unroll") for (int g = 0; g < 12; g++) {                             \
            float pre = fmaf(WIs[g][0], (x0),                                        \
                        fmaf(WIs[g][1], (x1),                                        \
                        fmaf(WIs[g][2], (x2),                                        \
                        fmaf(WHs[g][0], h0,                                          \
                        fmaf(WHs[g][1], h1,                                          \
                        fmaf(WHs[g][2], h2, BSs[g]))))));                            \
            th[g] = tanhx(pre);                                                      \
        }                                                                            \
        float i0 = fmaf(0.5f, th[0], 0.5f), i1 = fmaf(0.5f, th[1], 0.5f), i2 = fmaf(0.5f, th[2], 0.5f); \
        float f0 = fmaf(0.5f, th[3], 0.5f), f1 = fmaf(0.5f, th[4], 0.5f), f2 = fmaf(0.5f, th[5], 0.5f); \
        float o0 = fmaf(0.5f, th[9], 0.5f), o1 = fmaf(0.5f, th[10], 0.5f), o2 = fmaf(0.5f, th[11], 0.5f); \
        c0 = fmaf(f0, c0, i0 * th[6]);                                               \
        c1 = fmaf(f1, c1, i1 * th[7]);                                               \
        c2 = fmaf(f2, c2, i2 * th[8]);                                               \
        h0 = o0 * tanhx(c0); h1 = o1 * tanhx(c1); h2 = o2 * tanhx(c2);               \
    } while (0)

__global__ __launch_bounds__(BT) void gaze_kernel(
    const float* __restrict__ dir, const float* __restrict__ R,
    const float* __restrict__ Wih, const float* __restrict__ Whh,
    const float* __restrict__ bih, const float* __restrict__ bhh,
    float* __restrict__ out, int B, int T, int nback)
{
    __shared__ float4 sbuf[2][NQ * BT];           // 2 x 9216 B
    __shared__ float  sout[3 * C * BT];           // 3072 B

    const int half = T >> 1;
    const int t9q = (T * 9) >> 2;
    const size_t T3 = (size_t)T * 3;
    const int tid = threadIdx.x;
    const int nchunks = half / C;                 // 8

    if ((int)blockIdx.x < nback) {
        // ============ fused backward chain + scalar LSTM: 32 b's ============
        const int bbase = blockIdx.x * BT;

        // one-shot scalar register weights (prescaled)
        float WIs[12][3], WHs[12][3], BSs[12];
#pragma unroll
        for (int g = 0; g < 12; g++) {
            const float sc = (g >= 6 && g <= 8) ? 1.0f : 0.5f;
#pragma unroll
            for (int j = 0; j < 3; j++) {
                WIs[g][j] = __ldg(Wih + g * 3 + j) * sc;
                WHs[g][j] = __ldg(Whh + g * 3 + j) * sc;
            }
            BSs[g] = (__ldg(bih + g) + __ldg(bhh + g)) * sc;
        }

        const float d0 = __ldg(dir + (size_t)(bbase + tid) * 3 + 0);
        const float d1 = __ldg(dir + (size_t)(bbase + tid) * 3 + 1);
        const float d2 = __ldg(dir + (size_t)(bbase + tid) * 3 + 2);
        float v0 = d0, v1 = d1, v2 = d2;
        float h0 = 0.f, h1 = 0.f, h2 = 0.f, c0 = 0.f, c1 = 0.f, c2 = 0.f;

        const float4* R4 = (const float4*)R + (size_t)bbase * t9q;
        float* oblk = out + (size_t)bbase * T3;

        stage_chain(sbuf[0], R4 + (((half - C) * 9) >> 2), t9q, tid);
        CP_COMMIT();

        for (int cc = 0; cc < nchunks; cc++) {
            if (cc + 1 < nchunks) {
                stage_chain(sbuf[(cc + 1) & 1], R4 + (((half - C * (cc + 2)) * 9) >> 2), t9q, tid);
                CP_COMMIT(); CP_WAIT1();
            } else CP_WAIT0();
            __syncwarp();

            const float4* buf = sbuf[cc & 1];
            // steps s = 4j+k use matrix M = 7-s:
            // QA = {15,13,11,9}[k] - 9j (exact: 36j % 4 == 0), OFF = {3,2,1,0}[k].
#pragma unroll 1
            for (int j = 0; j < 2; j++) {
                const int qb = 9 * j;
                int eo = 12 * j;
#pragma unroll
                for (int k = 0; k < 4; k++) {
                    float A[9];
                    switch (k) {
                        case 0:  loadA_r<3>(A, buf, 15 - qb, tid); break;
                        case 1:  loadA_r<2>(A, buf, 13 - qb, tid); break;
                        case 2:  loadA_r<1>(A, buf, 11 - qb, tid); break;
                        default: loadA_r<0>(A, buf,  9 - qb, tid); break;
                    }
                    // v = A^T v
                    float n0 = fmaf(A[6], v2, fmaf(A[3], v1, A[0] * v0));
                    float n1 = fmaf(A[7], v2, fmaf(A[4], v1, A[1] * v0));
                    float n2 = fmaf(A[8], v2, fmaf(A[5], v1, A[2] * v0));
                    v0 = n0; v1 = n1; v2 = n2;
                    sout[(eo + 0) * BT + (tid ^ (eo + 0))] = v0;
                    sout[(eo + 1) * BT + (tid ^ (eo + 1))] = v1;
                    sout[(eo + 2) * BT + (tid ^ (eo + 2))] = v2;
                    eo += 3;

                    LSTM_STEP(v0, v1, v2);         // consumes x_t = dirs[8cc+4j+k]
                }
            }
            __syncwarp();
            store_chain<3 * C>(oblk + (size_t)(C * cc) * 3, T3, sout, tid);
            __syncwarp();
        }

        // final LSTM step consumes dir; h is the output row at t = half
        LSTM_STEP(d0, d1, d2);
        float* ob = out + (size_t)(bbase + tid) * T3 + (size_t)half * 3;
        ob[0] = h0; ob[1] = h1; ob[2] = h2;
    } else {
        // ============ forward chain: 32 b's (unchanged) ============
        const int bbase = ((int)blockIdx.x - nback) * BT;
        const int nsteps = T - 1 - half;           // 63

        float v0 = __ldg(dir + (size_t)(bbase + tid) * 3 + 0);
        float v1 = __ldg(dir + (size_t)(bbase + tid) * 3 + 1);
        float v2 = __ldg(dir + (size_t)(bbase + tid) * 3 + 2);

        const float4* R4 = (const float4*)R + (size_t)bbase * t9q;
        float* oblk = out + (size_t)bbase * T3;

        stage_chain(sbuf[0], R4 + ((half * 9) >> 2), t9q, tid);
        CP_COMMIT();
        for (int cc = 0; cc < nchunks; cc++) {
            if (cc + 1 < nchunks) {
                stage_chain(sbuf[(cc + 1) & 1], R4 + (((half + C * (cc + 1)) * 9) >> 2), t9q, tid);
                CP_COMMIT(); CP_WAIT1();
            } else CP_WAIT0();
            __syncwarp();

            const float4* buf = sbuf[cc & 1];
            const int ns = (nsteps - C * cc) < C ? (nsteps - C * cc) : C;
#pragma unroll
            for (int s = 0; s < C; s++) {
                if (s < ns) {
                    float A[9];
                    switch (s) {
                        case 0: loadA<0>(A, buf, tid); break;
                        case 1: loadA<1>(A, buf, tid); break;
                        case 2: loadA<2>(A, buf, tid); break;
                        case 3: loadA<3>(A, buf, tid); break;
                        case 4: loadA<4>(A, buf, tid); break;
                        case 5: loadA<5>(A, buf, tid); break;
                        case 6: loadA<6>(A, buf, tid); break;
                        default: loadA<7>(A, buf, tid); break;
                    }
                    // v = A v
                    float n0 = fmaf(A[2], v2, fmaf(A[1], v1, A[0] * v0));
                    float n1 = fmaf(A[5], v2, fmaf(A[4], v1, A[3] * v0));
                    float n2 = fmaf(A[8], v2, fmaf(A[7], v1, A[6] * v0));
                    v0 = n0; v1 = n1; v2 = n2;
                    const int eo = 3 * s;
                    sout[(eo + 0) * BT + (tid ^ (eo + 0))] = v0;
                    sout[(eo + 1) * BT + (tid ^ (eo + 1))] = v1;
                    sout[(eo + 2) * BT + (tid ^ (eo + 2))] = v2;
                }
            }
            __syncwarp();
            float* gdst = oblk + (size_t)(half + 1 + C * cc) * 3;
            if (ns == C) store_chain<3 * C>(gdst, T3, sout, tid);
            else         store_chain<21>(gdst, T3, sout, tid);   // last: 7 steps
            __syncwarp();
        }
    }
}

extern "C" void kernel_launch(void* const* d_in, const int* in_sizes, int n_in,
                              void* d_out, int out_size)
{
    const float* dir = (const float*)d_in[0];
    const float* R   = (const float*)d_in[1];
    const float* Wih = (const float*)d_in[2];
    const float* Whh = (const float*)d_in[3];
    const float* bih = (const float*)d_in[4];
    const float* bhh = (const float*)d_in[5];
    float* out = (float*)d_out;

    const int B = in_sizes[0] / 3;
    const int T = in_sizes[1] / (B * 9);
    const int nback = B / BT;   // 512
    const int nfwd  = B / BT;   // 512

    gaze_kernel<<<nback + nfwd, BT>>>(dir, R, Wih, Whh, bih, bhh, out, B, T, nback);
}